// round 11
// baseline (speedup 1.0000x reference)
#include <cuda_runtime.h>

// Problem constants
#define NN 50000
#define NE 600000
#define NBLK 196                     // ceil(NN/256)

// Float scratch offsets (no zeroing needed; fully overwritten each replay)
#define OFF_RS_OUT 0
#define OFF_RS_IN  50000
#define OFF_T1     100000            // 50000*64
#define OFF_AGG1   3300000           // 50000*64
#define OFF_T2     6500000           // 50000*32
#define OFF_T3     8100000           // 50000*32
#define OFF_AGG3   9700000           // 50000*32
#define SCRATCH_TOTAL 11300000       // 45.2 MB

// Int scratch offsets
#define ICNT_SRC 0                   // 50000 out-degree counts
#define ICNT_DST 50000               // 50000 in-degree counts (consumed by fill)
#define IOFFS    100000              // 50001 CSR row offsets
#define ICSR     150004              // 600000 src ids grouped by dst
#define IBSUM    750004              // 196 scan block sums
#define IBASE    750200              // 196 scan block bases
#define INT_TOTAL 750396
#define IZERO    100000              // zero [0, IZERO) ints each replay

__device__ __align__(16) float g_scratch[SCRATCH_TOTAL];
__device__ __align__(16) int   g_int[INT_TOTAL];

typedef unsigned long long u64;

// ---- packed fp32x2 helpers (bit-exact 2x fp32) ----
__device__ __forceinline__ u64 fma2(u64 a, u64 b, u64 c) {
    u64 d;
    asm("fma.rn.f32x2 %0, %1, %2, %3;" : "=l"(d) : "l"(a), "l"(b), "l"(c));
    return d;
}
__device__ __forceinline__ u64 pack2(float x, float y) {
    u64 r;
    asm("mov.b64 %0, {%1, %2};" : "=l"(r) : "f"(x), "f"(y));
    return r;
}

// ---------------------------------------------------------------------------
// CSR build kernels (discrete — measured faster than persistent variant)
// ---------------------------------------------------------------------------
__global__ void zero_kernel() {
    int i = blockIdx.x * blockDim.x + threadIdx.x;
    if (i < IZERO / 4) ((int4*)g_int)[i] = make_int4(0, 0, 0, 0);
}

__global__ void count_kernel(const int* __restrict__ src, const int* __restrict__ dst) {
    int i = blockIdx.x * blockDim.x + threadIdx.x;
    if (i >= NE) return;
    atomicAdd(&g_int[ICNT_SRC + __ldg(&src[i])], 1);
    atomicAdd(&g_int[ICNT_DST + __ldg(&dst[i])], 1);
}

__global__ void __launch_bounds__(256) scan_blocksum_rsqrt() {
    int i = blockIdx.x * 256 + threadIdx.x;
    int v = 0;
    if (i < NN) {
        v = g_int[ICNT_DST + i];
        g_scratch[OFF_RS_IN  + i] = rsqrtf(fmaxf((float)v, 1.0f));
        g_scratch[OFF_RS_OUT + i] = rsqrtf(fmaxf((float)g_int[ICNT_SRC + i], 1.0f));
    }
    int s = v;
    #pragma unroll
    for (int o = 16; o; o >>= 1) s += __shfl_down_sync(0xffffffffu, s, o);
    __shared__ int ws[8];
    if ((threadIdx.x & 31) == 0) ws[threadIdx.x >> 5] = s;
    __syncthreads();
    if (threadIdx.x == 0) {
        int r = 0;
        #pragma unroll
        for (int k = 0; k < 8; k++) r += ws[k];
        g_int[IBSUM + blockIdx.x] = r;
    }
}

__global__ void __launch_bounds__(256) scan_bases() {
    int t = threadIdx.x;
    int v = (t < NBLK) ? g_int[IBSUM + t] : 0;
    int lane = t & 31, w = t >> 5;
    int x = v;
    #pragma unroll
    for (int o = 1; o < 32; o <<= 1) {
        int y = __shfl_up_sync(0xffffffffu, x, o);
        if (lane >= o) x += y;
    }
    __shared__ int ws[8], wb[8];
    if (lane == 31) ws[w] = x;
    __syncthreads();
    if (t == 0) {
        int r = 0;
        #pragma unroll
        for (int k = 0; k < 8; k++) { wb[k] = r; r += ws[k]; }
    }
    __syncthreads();
    if (t < NBLK) g_int[IBASE + t] = x - v + wb[w];
}

__global__ void __launch_bounds__(256) scan_final() {
    int i = blockIdx.x * 256 + threadIdx.x;
    int v = (i < NN) ? g_int[ICNT_DST + i] : 0;
    int lane = threadIdx.x & 31, w = threadIdx.x >> 5;
    int x = v;
    #pragma unroll
    for (int o = 1; o < 32; o <<= 1) {
        int y = __shfl_up_sync(0xffffffffu, x, o);
        if (lane >= o) x += y;
    }
    __shared__ int ws[8], wb[8];
    if (lane == 31) ws[w] = x;
    __syncthreads();
    if (threadIdx.x == 0) {
        int r = 0;
        #pragma unroll
        for (int k = 0; k < 8; k++) { wb[k] = r; r += ws[k]; }
    }
    __syncthreads();
    int excl = x - v + wb[w] + g_int[IBASE + blockIdx.x];
    if (i < NN) g_int[IOFFS + i] = excl;
    if (i == NN) g_int[IOFFS + NN] = NE;
}

__global__ void fill_kernel(const int* __restrict__ src, const int* __restrict__ dst) {
    int i = blockIdx.x * blockDim.x + threadIdx.x;
    if (i >= NE) return;
    int s = __ldg(&src[i]);
    int d = __ldg(&dst[i]);
    int c = atomicSub(&g_int[ICNT_DST + d], 1);
    g_int[ICSR + g_int[IOFFS + d] + c - 1] = s;
}

// ---------------------------------------------------------------------------
// Warp-per-node pull SpMM (32/(F/4) edges per iter; shfl fold; one store).
// EPI=0: plain store. EPI=1 (F=32): z = sum*rs_in + b2 -> out0; t3=z*rs_out -> out1.
// ---------------------------------------------------------------------------
template<int F, int EPI>
__global__ void __launch_bounds__(256) pull_spmm(const float* __restrict__ tin,
                                                 float* __restrict__ out0,
                                                 const float* __restrict__ b2,
                                                 float* __restrict__ out1)
{
    constexpr int C   = F / 4;
    constexpr int EPW = 32 / C;
    int gid = (blockIdx.x * 256 + threadIdx.x) >> 5;
    if (gid >= NN) return;
    int lane  = threadIdx.x & 31;
    int sub   = lane / C;
    int laneC = lane % C;

    int s0 = __ldg(&g_int[IOFFS + gid]);
    int s1 = __ldg(&g_int[IOFFS + gid + 1]);
    const int* csr = g_int + ICSR;

    float4 acc = make_float4(0.f, 0.f, 0.f, 0.f);
    for (int j = s0 + sub; j < s1; j += EPW) {
        int sidx = __ldg(&csr[j]);
        float4 v = __ldg((const float4*)(tin + (size_t)sidx * F + 4 * laneC));
        acc.x += v.x; acc.y += v.y; acc.z += v.z; acc.w += v.w;
    }
    #pragma unroll
    for (int o = 16; o >= C; o >>= 1) {
        acc.x += __shfl_down_sync(0xffffffffu, acc.x, o);
        acc.y += __shfl_down_sync(0xffffffffu, acc.y, o);
        acc.z += __shfl_down_sync(0xffffffffu, acc.z, o);
        acc.w += __shfl_down_sync(0xffffffffu, acc.w, o);
    }
    if (lane < C) {
        if (EPI == 0) {
            *(float4*)(out0 + (size_t)gid * F + 4 * laneC) = acc;
        } else {
            float rin  = g_scratch[OFF_RS_IN + gid];
            float rout = g_scratch[OFF_RS_OUT + gid];
            float4 b = __ldg((const float4*)&b2[4 * laneC]);
            float4 z;
            z.x = fmaf(acc.x, rin, b.x);
            z.y = fmaf(acc.y, rin, b.y);
            z.z = fmaf(acc.z, rin, b.z);
            z.w = fmaf(acc.w, rin, b.w);
            *(float4*)(out0 + (size_t)gid * F + 4 * laneC) = z;
            float4 t;
            t.x = z.x * rout; t.y = z.y * rout; t.z = z.z * rout; t.w = z.w * rout;
            *(float4*)(out1 + (size_t)gid * F + 4 * laneC) = t;
        }
    }
}

// ---------------------------------------------------------------------------
// Packed-f32x2 register-tiled GEMM. Nodes processed in PAIRS inside the
// f32x2 lanes: a-operand = LDS.64 of two adjacent nodes from the transposed
// sX[k][node] tile; b-operand = W pre-duplicated {w,w} in smem. Per k:
// (TN/2)*8 FMA2 instead of TN*8 FFMA -> 2x fma-pipe throughput, bit-exact.
//   MODE_IN : 0 raw, 1 relu(v*rs_in[n] + bin[k]), 2 v*rs_in[n]
//   MODE_OUT: 0 raw, 1 *rs_out[n],               2 +bout[j]
// ---------------------------------------------------------------------------
template<int K, int J, int KC, int TN, int MODE_IN, int MODE_OUT>
__global__ void __launch_bounds__(256) gemm_kernel(
    const float* __restrict__ X, const float* __restrict__ W,
    const float* __restrict__ rs_in, const float* __restrict__ bin,
    const float* __restrict__ rs_out, const float* __restrict__ bout,
    float* __restrict__ out)
{
    constexpr int JV = J / 8;            // column lanes (8 cols each)
    constexpr int NT = 256 / JV;         // thread rows
    constexpr int NB = NT * TN;          // nodes per block
    constexpr int NP = TN / 2;           // node pairs per thread

    __shared__ float2 sWd[KC * J];       // duplicated {w,w} pairs, [k][j]
    __shared__ float  sX[KC * NB];       // transposed [k][node]
    __shared__ float  sRS[NB];

    const int nrow = threadIdx.x / JV;
    const int jv   = threadIdx.x % JV;
    const int base = blockIdx.x * NB;

    if (MODE_OUT == 1 && threadIdx.x < NB) {
        int n = base + threadIdx.x;
        sRS[threadIdx.x] = (n < NN) ? __ldg(&rs_out[n]) : 0.f;
    }

    u64 acc[NP][8];
    #pragma unroll
    for (int c = 0; c < 8; c++) {
        u64 init = 0;
        if (MODE_OUT == 2) {
            float b = __ldg(&bout[8 * jv + c]);
            init = pack2(b, b);
        }
        #pragma unroll
        for (int p = 0; p < NP; p++) acc[p][c] = init;
    }

    #pragma unroll 1
    for (int k0 = 0; k0 < K; k0 += KC) {
        __syncthreads();
        // Stage W chunk, duplicated into pairs
        for (int i = threadIdx.x; i < KC * J; i += 256) {
            int kk = i / J, j = i % J;
            float w = __ldg(&W[(size_t)(k0 + kk) * J + j]);
            sWd[kk * J + j] = make_float2(w, w);
        }
        // Stage X chunk transposed: sX[k][node]
        for (int i = threadIdx.x; i < NB * (KC / 4); i += 256) {
            int nl = i % NB;
            int kc = i / NB;
            int n = base + nl;
            float4 v = make_float4(0.f, 0.f, 0.f, 0.f);
            if (n < NN) {
                v = __ldg((const float4*)&X[(size_t)n * K + k0 + 4 * kc]);
                if (MODE_IN == 1) {
                    float r = __ldg(&rs_in[n]);
                    float4 b = __ldg((const float4*)&bin[k0 + 4 * kc]);
                    v.x = fmaxf(fmaf(v.x, r, b.x), 0.f);
                    v.y = fmaxf(fmaf(v.y, r, b.y), 0.f);
                    v.z = fmaxf(fmaf(v.z, r, b.z), 0.f);
                    v.w = fmaxf(fmaf(v.w, r, b.w), 0.f);
                } else if (MODE_IN == 2) {
                    float r = __ldg(&rs_in[n]);
                    v.x *= r; v.y *= r; v.z *= r; v.w *= r;
                }
            }
            sX[(4 * kc + 0) * NB + nl] = v.x;
            sX[(4 * kc + 1) * NB + nl] = v.y;
            sX[(4 * kc + 2) * NB + nl] = v.z;
            sX[(4 * kc + 3) * NB + nl] = v.w;
        }
        __syncthreads();

        #pragma unroll 4
        for (int k = 0; k < KC; k++) {
            const u64* wrow = (const u64*)&sWd[k * J + 8 * jv];
            u64 wp[8];
            #pragma unroll
            for (int c = 0; c < 8; c++) wp[c] = wrow[c];
            const u64* xrow = (const u64*)&sX[k * NB + nrow * TN];
            #pragma unroll
            for (int p = 0; p < NP; p++) {
                u64 xp = xrow[p];
                #pragma unroll
                for (int c = 0; c < 8; c++)
                    acc[p][c] = fma2(xp, wp[c], acc[p][c]);
            }
        }
    }

    // Store: unpack node pairs
    #pragma unroll
    for (int t = 0; t < TN; t++) {
        int nl = nrow * TN + t;
        int n = base + nl;
        if (n < NN) {
            int p = t >> 1, hi = t & 1;
            float o[8];
            #pragma unroll
            for (int c = 0; c < 8; c++) {
                float2 f = *(float2*)&acc[p][c];
                o[c] = hi ? f.y : f.x;
            }
            if (MODE_OUT == 1) {
                float r = sRS[nl];
                #pragma unroll
                for (int c = 0; c < 8; c++) o[c] *= r;
            }
            *(float4*)&out[(size_t)n * J + 8 * jv] =
                make_float4(o[0], o[1], o[2], o[3]);
            *(float4*)&out[(size_t)n * J + 8 * jv + 4] =
                make_float4(o[4], o[5], o[6], o[7]);
        }
    }
}

// ---------------------------------------------------------------------------
extern "C" void kernel_launch(void* const* d_in, const int* in_sizes, int n_in,
                              void* d_out, int out_size)
{
    const float* features = (const float*)d_in[0];
    const int*   src      = (const int*)d_in[1];
    const int*   dst      = (const int*)d_in[2];
    const float* W1       = (const float*)d_in[3];
    const float* b1       = (const float*)d_in[4];
    const float* W2       = (const float*)d_in[5];
    const float* b2       = (const float*)d_in[6];
    const float* W3       = (const float*)d_in[7];
    const float* b3       = (const float*)d_in[8];

    float* z_out = (float*)d_out;                    // [50000, 32]
    float* recon = (float*)d_out + (size_t)NN * 32;  // [50000, 128]

    float* sp = nullptr;
    cudaGetSymbolAddress((void**)&sp, g_scratch);
    float* rs_out = sp + OFF_RS_OUT;
    float* rs_in  = sp + OFF_RS_IN;
    float* t1     = sp + OFF_T1;
    float* agg1   = sp + OFF_AGG1;
    float* t2     = sp + OFF_T2;
    float* t3     = sp + OFF_T3;
    float* agg3   = sp + OFF_AGG3;

    const int TB = 256;
    const int SPMM_BLKS = (NN * 32 + TB - 1) / TB;   // one warp per node

    // CSR build + norms (discrete launches — measured best)
    zero_kernel<<<(IZERO / 4 + TB - 1) / TB, TB>>>();
    count_kernel<<<(NE + TB - 1) / TB, TB>>>(src, dst);
    scan_blocksum_rsqrt<<<NBLK, 256>>>();
    scan_bases<<<1, 256>>>();
    scan_final<<<NBLK, 256>>>();
    fill_kernel<<<(NE + TB - 1) / TB, TB>>>(src, dst);

    // Layer 1: t1 = (X @ W1) * rs_out ; agg1 = A t1   (TN=8, NB=256, KC=16)
    gemm_kernel<128, 64, 16, 8, 0, 1><<<(NN + 255) / 256, TB>>>(
        features, W1, nullptr, nullptr, rs_out, nullptr, t1);
    pull_spmm<64, 0><<<SPMM_BLKS, TB>>>(t1, agg1, nullptr, nullptr);

    // Layer 2: t2 = (relu(agg1*rs_in + b1) @ W2) * rs_out (TN=4, NB=256, KC=32)
    //   then fused pull: z = (A t2)*rs_in + b2 -> z_out ; t3 = z*rs_out
    gemm_kernel<64, 32, 32, 4, 1, 1><<<(NN + 255) / 256, TB>>>(
        agg1, W2, rs_in, b1, rs_out, nullptr, t2);
    pull_spmm<32, 1><<<SPMM_BLKS, TB>>>(t2, z_out, b2, t3);

    // Layer 3: agg3 = A t3 ; recon = (agg3*rs_in) @ W3 + b3 (TN=8, NB=128, KC=16)
    pull_spmm<32, 0><<<SPMM_BLKS, TB>>>(t3, agg3, nullptr, nullptr);
    gemm_kernel<32, 128, 16, 8, 2, 2><<<(NN + 127) / 128, TB>>>(
        agg3, W3, rs_in, nullptr, nullptr, b3, recon);
}

// round 13
// speedup vs baseline: 1.5354x; 1.5354x over previous
#include <cuda_runtime.h>

// Problem constants
#define NN 50000
#define NE 600000
#define NBLK 196                     // ceil(NN/256)

// Float scratch offsets (no zeroing needed; fully overwritten each replay)
#define OFF_RS_OUT 0
#define OFF_RS_IN  50000
#define OFF_T1     100000            // 50000*64
#define OFF_AGG1   3300000           // 50000*64
#define OFF_T2     6500000           // 50000*32
#define OFF_T3     8100000           // 50000*32
#define OFF_AGG3   9700000           // 50000*32
#define SCRATCH_TOTAL 11300000       // 45.2 MB

// Int scratch offsets
#define ICNT_SRC 0                   // 50000 out-degree counts
#define ICNT_DST 50000               // 50000 in-degree counts (consumed by fill)
#define IOFFS    100000              // 50001 CSR row offsets
#define ICSR     150004              // 600000 src ids grouped by dst
#define IBSUM    750004              // 196 scan block sums
#define IBASE    750200              // 196 scan block bases
#define INT_TOTAL 750396
#define IZERO    100000              // zero [0, IZERO) ints each replay

__device__ __align__(16) float g_scratch[SCRATCH_TOTAL];
__device__ __align__(16) int   g_int[INT_TOTAL];

// ---------------------------------------------------------------------------
// CSR build kernels (discrete — measured best)
// ---------------------------------------------------------------------------
__global__ void zero_kernel() {
    int i = blockIdx.x * blockDim.x + threadIdx.x;
    if (i < IZERO / 4) ((int4*)g_int)[i] = make_int4(0, 0, 0, 0);
}

__global__ void count_kernel(const int* __restrict__ src, const int* __restrict__ dst) {
    int i = blockIdx.x * blockDim.x + threadIdx.x;
    if (i >= NE) return;
    atomicAdd(&g_int[ICNT_SRC + __ldg(&src[i])], 1);
    atomicAdd(&g_int[ICNT_DST + __ldg(&dst[i])], 1);
}

__global__ void __launch_bounds__(256) scan_blocksum_rsqrt() {
    int i = blockIdx.x * 256 + threadIdx.x;
    int v = 0;
    if (i < NN) {
        v = g_int[ICNT_DST + i];
        g_scratch[OFF_RS_IN  + i] = rsqrtf(fmaxf((float)v, 1.0f));
        g_scratch[OFF_RS_OUT + i] = rsqrtf(fmaxf((float)g_int[ICNT_SRC + i], 1.0f));
    }
    int s = v;
    #pragma unroll
    for (int o = 16; o; o >>= 1) s += __shfl_down_sync(0xffffffffu, s, o);
    __shared__ int ws[8];
    if ((threadIdx.x & 31) == 0) ws[threadIdx.x >> 5] = s;
    __syncthreads();
    if (threadIdx.x == 0) {
        int r = 0;
        #pragma unroll
        for (int k = 0; k < 8; k++) r += ws[k];
        g_int[IBSUM + blockIdx.x] = r;
    }
}

__global__ void __launch_bounds__(256) scan_bases() {
    int t = threadIdx.x;
    int v = (t < NBLK) ? g_int[IBSUM + t] : 0;
    int lane = t & 31, w = t >> 5;
    int x = v;
    #pragma unroll
    for (int o = 1; o < 32; o <<= 1) {
        int y = __shfl_up_sync(0xffffffffu, x, o);
        if (lane >= o) x += y;
    }
    __shared__ int ws[8], wb[8];
    if (lane == 31) ws[w] = x;
    __syncthreads();
    if (t == 0) {
        int r = 0;
        #pragma unroll
        for (int k = 0; k < 8; k++) { wb[k] = r; r += ws[k]; }
    }
    __syncthreads();
    if (t < NBLK) g_int[IBASE + t] = x - v + wb[w];
}

__global__ void __launch_bounds__(256) scan_final() {
    int i = blockIdx.x * 256 + threadIdx.x;
    int v = (i < NN) ? g_int[ICNT_DST + i] : 0;
    int lane = threadIdx.x & 31, w = threadIdx.x >> 5;
    int x = v;
    #pragma unroll
    for (int o = 1; o < 32; o <<= 1) {
        int y = __shfl_up_sync(0xffffffffu, x, o);
        if (lane >= o) x += y;
    }
    __shared__ int ws[8], wb[8];
    if (lane == 31) ws[w] = x;
    __syncthreads();
    if (threadIdx.x == 0) {
        int r = 0;
        #pragma unroll
        for (int k = 0; k < 8; k++) { wb[k] = r; r += ws[k]; }
    }
    __syncthreads();
    int excl = x - v + wb[w] + g_int[IBASE + blockIdx.x];
    if (i < NN) g_int[IOFFS + i] = excl;
    if (i == NN) g_int[IOFFS + NN] = NE;
}

__global__ void fill_kernel(const int* __restrict__ src, const int* __restrict__ dst) {
    int i = blockIdx.x * blockDim.x + threadIdx.x;
    if (i >= NE) return;
    int s = __ldg(&src[i]);
    int d = __ldg(&dst[i]);
    int c = atomicSub(&g_int[ICNT_DST + d], 1);
    g_int[ICSR + g_int[IOFFS + d] + c - 1] = s;
}

// ---------------------------------------------------------------------------
// Warp-per-node pull SpMM (32/(F/4) edges per iter; shfl fold; one store).
// EPI=0: plain store. EPI=1 (F=32): z = sum*rs_in + b2 -> out0; t3=z*rs_out -> out1.
// ---------------------------------------------------------------------------
template<int F, int EPI>
__global__ void __launch_bounds__(256) pull_spmm(const float* __restrict__ tin,
                                                 float* __restrict__ out0,
                                                 const float* __restrict__ b2,
                                                 float* __restrict__ out1)
{
    constexpr int C   = F / 4;
    constexpr int EPW = 32 / C;
    int gid = (blockIdx.x * 256 + threadIdx.x) >> 5;
    if (gid >= NN) return;
    int lane  = threadIdx.x & 31;
    int sub   = lane / C;
    int laneC = lane % C;

    int s0 = __ldg(&g_int[IOFFS + gid]);
    int s1 = __ldg(&g_int[IOFFS + gid + 1]);
    const int* csr = g_int + ICSR;

    float4 acc = make_float4(0.f, 0.f, 0.f, 0.f);
    for (int j = s0 + sub; j < s1; j += EPW) {
        int sidx = __ldg(&csr[j]);
        float4 v = __ldg((const float4*)(tin + (size_t)sidx * F + 4 * laneC));
        acc.x += v.x; acc.y += v.y; acc.z += v.z; acc.w += v.w;
    }
    #pragma unroll
    for (int o = 16; o >= C; o >>= 1) {
        acc.x += __shfl_down_sync(0xffffffffu, acc.x, o);
        acc.y += __shfl_down_sync(0xffffffffu, acc.y, o);
        acc.z += __shfl_down_sync(0xffffffffu, acc.z, o);
        acc.w += __shfl_down_sync(0xffffffffu, acc.w, o);
    }
    if (lane < C) {
        if (EPI == 0) {
            *(float4*)(out0 + (size_t)gid * F + 4 * laneC) = acc;
        } else {
            float rin  = g_scratch[OFF_RS_IN + gid];
            float rout = g_scratch[OFF_RS_OUT + gid];
            float4 b = __ldg((const float4*)&b2[4 * laneC]);
            float4 z;
            z.x = fmaf(acc.x, rin, b.x);
            z.y = fmaf(acc.y, rin, b.y);
            z.z = fmaf(acc.z, rin, b.z);
            z.w = fmaf(acc.w, rin, b.w);
            *(float4*)(out0 + (size_t)gid * F + 4 * laneC) = z;
            float4 t;
            t.x = z.x * rout; t.y = z.y * rout; t.z = z.z * rout; t.w = z.w * rout;
            *(float4*)(out1 + (size_t)gid * F + 4 * laneC) = t;
        }
    }
}

// ---------------------------------------------------------------------------
// Register-tiled GEMM, transposed X tile (conflict-free LDS.128/LDS.64):
//   out[n, :J] = f_out( f_in(X[n, :K]) @ W )
//   TN in {2, 4, 8}. Smaller TN -> more threads -> higher occupancy.
//   MODE_IN : 0 raw, 1 relu(v*rs_in[n] + bin[k]), 2 v*rs_in[n]
//   MODE_OUT: 0 raw, 1 *rs_out[n],               2 +bout[j]
// ---------------------------------------------------------------------------
template<int K, int J, int KC, int TN, int MODE_IN, int MODE_OUT>
__global__ void __launch_bounds__(256) gemm_kernel(
    const float* __restrict__ X, const float* __restrict__ W,
    const float* __restrict__ rs_in, const float* __restrict__ bin,
    const float* __restrict__ rs_out, const float* __restrict__ bout,
    float* __restrict__ out)
{
    constexpr int JV = J / 8;            // column lanes (8 cols each)
    constexpr int NT = 256 / JV;         // thread rows
    constexpr int NB = NT * TN;          // nodes per block
    constexpr int XST = NB;              // transposed row stride

    __shared__ float sW[KC * J];
    __shared__ float sX[KC * XST];       // [k][node]
    __shared__ float sRS[NB];

    const int nrow = threadIdx.x / JV;
    const int jv   = threadIdx.x % JV;
    const int base = blockIdx.x * NB;

    if (MODE_OUT == 1 && threadIdx.x < NB) {
        int n = base + threadIdx.x;
        sRS[threadIdx.x] = (n < NN) ? __ldg(&rs_out[n]) : 0.f;
    }

    float4 acc[TN][2];
    #pragma unroll
    for (int t = 0; t < TN; t++)
        #pragma unroll
        for (int c = 0; c < 2; c++) {
            if (MODE_OUT == 2) acc[t][c] = __ldg((const float4*)&bout[8 * jv + 4 * c]);
            else               acc[t][c] = make_float4(0.f, 0.f, 0.f, 0.f);
        }

    #pragma unroll 1
    for (int k0 = 0; k0 < K; k0 += KC) {
        __syncthreads();
        for (int i = threadIdx.x; i < KC * J / 4; i += 256)
            ((float4*)sW)[i] = __ldg(&((const float4*)(W + (size_t)k0 * J))[i]);
        for (int i = threadIdx.x; i < NB * (KC / 4); i += 256) {
            int nl = i % NB;
            int kc = i / NB;
            int n = base + nl;
            float4 v = make_float4(0.f, 0.f, 0.f, 0.f);
            if (n < NN) {
                v = __ldg((const float4*)&X[(size_t)n * K + k0 + 4 * kc]);
                if (MODE_IN == 1) {
                    float r = __ldg(&rs_in[n]);
                    float4 b = __ldg((const float4*)&bin[k0 + 4 * kc]);
                    v.x = fmaxf(fmaf(v.x, r, b.x), 0.f);
                    v.y = fmaxf(fmaf(v.y, r, b.y), 0.f);
                    v.z = fmaxf(fmaf(v.z, r, b.z), 0.f);
                    v.w = fmaxf(fmaf(v.w, r, b.w), 0.f);
                } else if (MODE_IN == 2) {
                    float r = __ldg(&rs_in[n]);
                    v.x *= r; v.y *= r; v.z *= r; v.w *= r;
                }
            }
            sX[(4 * kc + 0) * XST + nl] = v.x;
            sX[(4 * kc + 1) * XST + nl] = v.y;
            sX[(4 * kc + 2) * XST + nl] = v.z;
            sX[(4 * kc + 3) * XST + nl] = v.w;
        }
        __syncthreads();

        #pragma unroll 4
        for (int k = 0; k < KC; k++) {
            float4 w0 = *(const float4*)&sW[k * J + 8 * jv];
            float4 w1 = *(const float4*)&sW[k * J + 8 * jv + 4];
            if constexpr (TN == 2) {
                float2 xa = *(const float2*)&sX[k * XST + nrow * TN];
                float xk2[2] = {xa.x, xa.y};
                #pragma unroll
                for (int t = 0; t < 2; t++) {
                    float xk = xk2[t];
                    acc[t][0].x = fmaf(xk, w0.x, acc[t][0].x);
                    acc[t][0].y = fmaf(xk, w0.y, acc[t][0].y);
                    acc[t][0].z = fmaf(xk, w0.z, acc[t][0].z);
                    acc[t][0].w = fmaf(xk, w0.w, acc[t][0].w);
                    acc[t][1].x = fmaf(xk, w1.x, acc[t][1].x);
                    acc[t][1].y = fmaf(xk, w1.y, acc[t][1].y);
                    acc[t][1].z = fmaf(xk, w1.z, acc[t][1].z);
                    acc[t][1].w = fmaf(xk, w1.w, acc[t][1].w);
                }
            } else {
                #pragma unroll
                for (int tt = 0; tt < TN / 4; tt++) {
                    float4 xa = *(const float4*)&sX[k * XST + nrow * TN + 4 * tt];
                    float xk4[4] = {xa.x, xa.y, xa.z, xa.w};
                    #pragma unroll
                    for (int q = 0; q < 4; q++) {
                        int t = 4 * tt + q;
                        float xk = xk4[q];
                        acc[t][0].x = fmaf(xk, w0.x, acc[t][0].x);
                        acc[t][0].y = fmaf(xk, w0.y, acc[t][0].y);
                        acc[t][0].z = fmaf(xk, w0.z, acc[t][0].z);
                        acc[t][0].w = fmaf(xk, w0.w, acc[t][0].w);
                        acc[t][1].x = fmaf(xk, w1.x, acc[t][1].x);
                        acc[t][1].y = fmaf(xk, w1.y, acc[t][1].y);
                        acc[t][1].z = fmaf(xk, w1.z, acc[t][1].z);
                        acc[t][1].w = fmaf(xk, w1.w, acc[t][1].w);
                    }
                }
            }
        }
    }

    #pragma unroll
    for (int t = 0; t < TN; t++) {
        int nl = nrow * TN + t;
        int n = base + nl;
        if (n < NN) {
            if (MODE_OUT == 1) {
                float r = sRS[nl];
                #pragma unroll
                for (int c = 0; c < 2; c++) {
                    acc[t][c].x *= r; acc[t][c].y *= r;
                    acc[t][c].z *= r; acc[t][c].w *= r;
                }
            }
            *(float4*)&out[(size_t)n * J + 8 * jv]     = acc[t][0];
            *(float4*)&out[(size_t)n * J + 8 * jv + 4] = acc[t][1];
        }
    }
}

// ---------------------------------------------------------------------------
extern "C" void kernel_launch(void* const* d_in, const int* in_sizes, int n_in,
                              void* d_out, int out_size)
{
    const float* features = (const float*)d_in[0];
    const int*   src      = (const int*)d_in[1];
    const int*   dst      = (const int*)d_in[2];
    const float* W1       = (const float*)d_in[3];
    const float* b1       = (const float*)d_in[4];
    const float* W2       = (const float*)d_in[5];
    const float* b2       = (const float*)d_in[6];
    const float* W3       = (const float*)d_in[7];
    const float* b3       = (const float*)d_in[8];

    float* z_out = (float*)d_out;                    // [50000, 32]
    float* recon = (float*)d_out + (size_t)NN * 32;  // [50000, 128]

    float* sp = nullptr;
    cudaGetSymbolAddress((void**)&sp, g_scratch);
    float* rs_out = sp + OFF_RS_OUT;
    float* rs_in  = sp + OFF_RS_IN;
    float* t1     = sp + OFF_T1;
    float* agg1   = sp + OFF_AGG1;
    float* t2     = sp + OFF_T2;
    float* t3     = sp + OFF_T3;
    float* agg3   = sp + OFF_AGG3;

    const int TB = 256;
    const int SPMM_BLKS = (NN * 32 + TB - 1) / TB;   // one warp per node

    // CSR build + norms (discrete launches — measured best)
    zero_kernel<<<(IZERO / 4 + TB - 1) / TB, TB>>>();
    count_kernel<<<(NE + TB - 1) / TB, TB>>>(src, dst);
    scan_blocksum_rsqrt<<<NBLK, 256>>>();
    scan_bases<<<1, 256>>>();
    scan_final<<<NBLK, 256>>>();
    fill_kernel<<<(NE + TB - 1) / TB, TB>>>(src, dst);

    // Layer 1: t1 = (X @ W1) * rs_out ; agg1 = A t1   (TN=4, NB=128, grid 391)
    gemm_kernel<128, 64, 32, 4, 0, 1><<<(NN + 127) / 128, TB>>>(
        features, W1, nullptr, nullptr, rs_out, nullptr, t1);
    pull_spmm<64, 0><<<SPMM_BLKS, TB>>>(t1, agg1, nullptr, nullptr);

    // Layer 2: t2 = (relu(agg1*rs_in + b1) @ W2) * rs_out (TN=2, NB=128, grid 391)
    //   then fused pull: z = (A t2)*rs_in + b2 -> z_out ; t3 = z*rs_out
    gemm_kernel<64, 32, 32, 2, 1, 1><<<(NN + 127) / 128, TB>>>(
        agg1, W2, rs_in, b1, rs_out, nullptr, t2);
    pull_spmm<32, 1><<<SPMM_BLKS, TB>>>(t2, z_out, b2, t3);

    // Layer 3: agg3 = A t3 ; recon = (agg3*rs_in) @ W3 + b3 (TN=4, NB=64, grid 782)
    pull_spmm<32, 0><<<SPMM_BLKS, TB>>>(t3, agg3, nullptr, nullptr);
    gemm_kernel<32, 128, 32, 4, 2, 2><<<(NN + 63) / 64, TB>>>(
        agg3, W3, rs_in, nullptr, nullptr, b3, recon);
}

// round 15
// speedup vs baseline: 1.5815x; 1.0300x over previous
#include <cuda_runtime.h>

// Problem constants
#define NN 50000
#define NE 600000
#define NBLK 196                     // ceil(NN/256)

// Float scratch offsets (no zeroing needed; fully overwritten each replay)
#define OFF_RS_OUT 0
#define OFF_RS_IN  50000
#define OFF_T1     100000            // 50000*64
#define OFF_AGG1   3300000           // 50000*64
#define OFF_T2     6500000           // 50000*32
#define OFF_T3     8100000           // 50000*32
#define OFF_AGG3   9700000           // 50000*32
#define SCRATCH_TOTAL 11300000       // 45.2 MB

// Int scratch offsets
// ICNT_SRC: zeroed inside gemm1 (after last read); ICNT_DST: self-zeroing
// (fill_kernel's atomicSub returns each count to exactly 0 every replay;
//  __device__ globals start zero-initialized for the first call).
#define ICNT_SRC 0                   // 50000 out-degree counts
#define ICNT_DST 50000               // 50000 in-degree counts (consumed by fill)
#define IOFFS    100000              // 50001 CSR row offsets
#define ICSR     150004              // 600000 src ids grouped by dst
#define IBSUM    750004              // 196 scan block sums
#define INT_TOTAL 750200

__device__ __align__(16) float g_scratch[SCRATCH_TOTAL];
__device__ __align__(16) int   g_int[INT_TOTAL];

// ---------------------------------------------------------------------------
// Degree histograms (counts arrive on a zeroed array — see invariant above)
// ---------------------------------------------------------------------------
__global__ void count_kernel(const int* __restrict__ src, const int* __restrict__ dst) {
    int i = blockIdx.x * blockDim.x + threadIdx.x;
    if (i >= NE) return;
    atomicAdd(&g_int[ICNT_SRC + __ldg(&src[i])], 1);
    atomicAdd(&g_int[ICNT_DST + __ldg(&dst[i])], 1);
}

// ---------------------------------------------------------------------------
// rsqrt norms + per-256-chunk sums of in-degrees -> IBSUM
// ---------------------------------------------------------------------------
__global__ void __launch_bounds__(256) scan_blocksum_rsqrt() {
    int i = blockIdx.x * 256 + threadIdx.x;
    int v = 0;
    if (i < NN) {
        v = g_int[ICNT_DST + i];
        g_scratch[OFF_RS_IN  + i] = rsqrtf(fmaxf((float)v, 1.0f));
        g_scratch[OFF_RS_OUT + i] = rsqrtf(fmaxf((float)g_int[ICNT_SRC + i], 1.0f));
    }
    int s = v;
    #pragma unroll
    for (int o = 16; o; o >>= 1) s += __shfl_down_sync(0xffffffffu, s, o);
    __shared__ int ws[8];
    if ((threadIdx.x & 31) == 0) ws[threadIdx.x >> 5] = s;
    __syncthreads();
    if (threadIdx.x == 0) {
        int r = 0;
        #pragma unroll
        for (int k = 0; k < 8; k++) r += ws[k];
        g_int[IBSUM + blockIdx.x] = r;
    }
}

// ---------------------------------------------------------------------------
// Final exclusive CSR offsets. Each block derives its own base by reducing
// IBSUM[j] for j < bid (196 ints -- cheaper than a separate bases kernel).
// ---------------------------------------------------------------------------
__global__ void __launch_bounds__(256) scan_final() {
    const int tid = threadIdx.x;
    const int bid = blockIdx.x;
    __shared__ int ws[8], wb[8];
    __shared__ int sbase;

    // Block base = sum of preceding chunk sums
    {
        int v = (tid < bid) ? g_int[IBSUM + tid] : 0;   // bid <= NBLK <= 256
        #pragma unroll
        for (int o = 16; o; o >>= 1) v += __shfl_down_sync(0xffffffffu, v, o);
        if ((tid & 31) == 0) ws[tid >> 5] = v;
        __syncthreads();
        if (tid == 0) {
            int r = 0;
            #pragma unroll
            for (int k = 0; k < 8; k++) r += ws[k];
            sbase = r;
        }
    }
    __syncthreads();

    int i = bid * 256 + tid;
    int v = (i < NN) ? g_int[ICNT_DST + i] : 0;
    int lane = tid & 31, w = tid >> 5;
    int x = v;
    #pragma unroll
    for (int o = 1; o < 32; o <<= 1) {
        int y = __shfl_up_sync(0xffffffffu, x, o);
        if (lane >= o) x += y;
    }
    if (lane == 31) ws[w] = x;
    __syncthreads();
    if (tid == 0) {
        int r = 0;
        #pragma unroll
        for (int k = 0; k < 8; k++) { wb[k] = r; r += ws[k]; }
    }
    __syncthreads();
    int excl = x - v + wb[w] + sbase;
    if (i < NN) g_int[IOFFS + i] = excl;
    if (i == NN) g_int[IOFFS + NN] = NE;
}

// ---------------------------------------------------------------------------
// CSR fill. atomicSub drains every ICNT_DST entry to exactly 0, restoring
// the zero-state invariant for the next replay's count_kernel.
// ---------------------------------------------------------------------------
__global__ void fill_kernel(const int* __restrict__ src, const int* __restrict__ dst) {
    int i = blockIdx.x * blockDim.x + threadIdx.x;
    if (i >= NE) return;
    int s = __ldg(&src[i]);
    int d = __ldg(&dst[i]);
    int c = atomicSub(&g_int[ICNT_DST + d], 1);
    g_int[ICSR + g_int[IOFFS + d] + c - 1] = s;
}

// ---------------------------------------------------------------------------
// Warp-per-node pull SpMM (32/(F/4) edges per iter; shfl fold; one store).
// EPI=0: plain store. EPI=1 (F=32): z = sum*rs_in + b2 -> out0; t3=z*rs_out -> out1.
// ---------------------------------------------------------------------------
template<int F, int EPI>
__global__ void __launch_bounds__(256) pull_spmm(const float* __restrict__ tin,
                                                 float* __restrict__ out0,
                                                 const float* __restrict__ b2,
                                                 float* __restrict__ out1)
{
    constexpr int C   = F / 4;
    constexpr int EPW = 32 / C;
    int gid = (blockIdx.x * 256 + threadIdx.x) >> 5;
    if (gid >= NN) return;
    int lane  = threadIdx.x & 31;
    int sub   = lane / C;
    int laneC = lane % C;

    int s0 = __ldg(&g_int[IOFFS + gid]);
    int s1 = __ldg(&g_int[IOFFS + gid + 1]);
    const int* csr = g_int + ICSR;

    float4 acc = make_float4(0.f, 0.f, 0.f, 0.f);
    for (int j = s0 + sub; j < s1; j += EPW) {
        int sidx = __ldg(&csr[j]);
        float4 v = __ldg((const float4*)(tin + (size_t)sidx * F + 4 * laneC));
        acc.x += v.x; acc.y += v.y; acc.z += v.z; acc.w += v.w;
    }
    #pragma unroll
    for (int o = 16; o >= C; o >>= 1) {
        acc.x += __shfl_down_sync(0xffffffffu, acc.x, o);
        acc.y += __shfl_down_sync(0xffffffffu, acc.y, o);
        acc.z += __shfl_down_sync(0xffffffffu, acc.z, o);
        acc.w += __shfl_down_sync(0xffffffffu, acc.w, o);
    }
    if (lane < C) {
        if (EPI == 0) {
            *(float4*)(out0 + (size_t)gid * F + 4 * laneC) = acc;
        } else {
            float rin  = g_scratch[OFF_RS_IN + gid];
            float rout = g_scratch[OFF_RS_OUT + gid];
            float4 b = __ldg((const float4*)&b2[4 * laneC]);
            float4 z;
            z.x = fmaf(acc.x, rin, b.x);
            z.y = fmaf(acc.y, rin, b.y);
            z.z = fmaf(acc.z, rin, b.z);
            z.w = fmaf(acc.w, rin, b.w);
            *(float4*)(out0 + (size_t)gid * F + 4 * laneC) = z;
            float4 t;
            t.x = z.x * rout; t.y = z.y * rout; t.z = z.z * rout; t.w = z.w * rout;
            *(float4*)(out1 + (size_t)gid * F + 4 * laneC) = t;
        }
    }
}

// ---------------------------------------------------------------------------
// Register-tiled GEMM, transposed X tile (conflict-free LDS.128 everywhere):
//   out[n, :J] = f_out( f_in(X[n, :K]) @ W )
//   MODE_IN : 0 raw, 1 relu(v*rs_in[n] + bin[k]), 2 v*rs_in[n]
//   MODE_OUT: 0 raw, 1 *rs_out[n],               2 +bout[j]
//   ZERO_CNT: if 1, this kernel also zeroes ICNT_SRC (runs after its last
//             reader; restores the zero-state invariant for the next replay)
// ---------------------------------------------------------------------------
template<int K, int J, int KC, int TN, int MODE_IN, int MODE_OUT, int ZERO_CNT>
__global__ void __launch_bounds__(256) gemm_kernel(
    const float* __restrict__ X, const float* __restrict__ W,
    const float* __restrict__ rs_in, const float* __restrict__ bin,
    const float* __restrict__ rs_out, const float* __restrict__ bout,
    float* __restrict__ out)
{
    constexpr int JV = J / 8;            // column lanes (8 cols each)
    constexpr int NT = 256 / JV;         // thread rows
    constexpr int NB = NT * TN;          // nodes per block
    constexpr int XST = NB;              // transposed row stride

    __shared__ float sW[KC * J];
    __shared__ float sX[KC * XST];       // [k][node]
    __shared__ float sRS[NB];

    if (ZERO_CNT) {
        int i = blockIdx.x * 256 + threadIdx.x;
        for (; i < NN; i += gridDim.x * 256) g_int[ICNT_SRC + i] = 0;
    }

    const int nrow = threadIdx.x / JV;
    const int jv   = threadIdx.x % JV;
    const int base = blockIdx.x * NB;

    if (MODE_OUT == 1 && threadIdx.x < NB) {
        int n = base + threadIdx.x;
        sRS[threadIdx.x] = (n < NN) ? __ldg(&rs_out[n]) : 0.f;
    }

    float4 acc[TN][2];
    #pragma unroll
    for (int t = 0; t < TN; t++)
        #pragma unroll
        for (int c = 0; c < 2; c++) {
            if (MODE_OUT == 2) acc[t][c] = __ldg((const float4*)&bout[8 * jv + 4 * c]);
            else               acc[t][c] = make_float4(0.f, 0.f, 0.f, 0.f);
        }

    #pragma unroll 1
    for (int k0 = 0; k0 < K; k0 += KC) {
        __syncthreads();
        for (int i = threadIdx.x; i < KC * J / 4; i += 256)
            ((float4*)sW)[i] = __ldg(&((const float4*)(W + (size_t)k0 * J))[i]);
        for (int i = threadIdx.x; i < NB * (KC / 4); i += 256) {
            int nl = i % NB;
            int kc = i / NB;
            int n = base + nl;
            float4 v = make_float4(0.f, 0.f, 0.f, 0.f);
            if (n < NN) {
                v = __ldg((const float4*)&X[(size_t)n * K + k0 + 4 * kc]);
                if (MODE_IN == 1) {
                    float r = __ldg(&rs_in[n]);
                    float4 b = __ldg((const float4*)&bin[k0 + 4 * kc]);
                    v.x = fmaxf(fmaf(v.x, r, b.x), 0.f);
                    v.y = fmaxf(fmaf(v.y, r, b.y), 0.f);
                    v.z = fmaxf(fmaf(v.z, r, b.z), 0.f);
                    v.w = fmaxf(fmaf(v.w, r, b.w), 0.f);
                } else if (MODE_IN == 2) {
                    float r = __ldg(&rs_in[n]);
                    v.x *= r; v.y *= r; v.z *= r; v.w *= r;
                }
            }
            sX[(4 * kc + 0) * XST + nl] = v.x;
            sX[(4 * kc + 1) * XST + nl] = v.y;
            sX[(4 * kc + 2) * XST + nl] = v.z;
            sX[(4 * kc + 3) * XST + nl] = v.w;
        }
        __syncthreads();

        #pragma unroll 4
        for (int k = 0; k < KC; k++) {
            float4 w0 = *(const float4*)&sW[k * J + 8 * jv];
            float4 w1 = *(const float4*)&sW[k * J + 8 * jv + 4];
            #pragma unroll
            for (int tt = 0; tt < TN / 4; tt++) {
                float4 xa = *(const float4*)&sX[k * XST + nrow * TN + 4 * tt];
                float xk4[4] = {xa.x, xa.y, xa.z, xa.w};
                #pragma unroll
                for (int q = 0; q < 4; q++) {
                    int t = 4 * tt + q;
                    float xk = xk4[q];
                    acc[t][0].x = fmaf(xk, w0.x, acc[t][0].x);
                    acc[t][0].y = fmaf(xk, w0.y, acc[t][0].y);
                    acc[t][0].z = fmaf(xk, w0.z, acc[t][0].z);
                    acc[t][0].w = fmaf(xk, w0.w, acc[t][0].w);
                    acc[t][1].x = fmaf(xk, w1.x, acc[t][1].x);
                    acc[t][1].y = fmaf(xk, w1.y, acc[t][1].y);
                    acc[t][1].z = fmaf(xk, w1.z, acc[t][1].z);
                    acc[t][1].w = fmaf(xk, w1.w, acc[t][1].w);
                }
            }
        }
    }

    #pragma unroll
    for (int t = 0; t < TN; t++) {
        int nl = nrow * TN + t;
        int n = base + nl;
        if (n < NN) {
            if (MODE_OUT == 1) {
                float r = sRS[nl];
                #pragma unroll
                for (int c = 0; c < 2; c++) {
                    acc[t][c].x *= r; acc[t][c].y *= r;
                    acc[t][c].z *= r; acc[t][c].w *= r;
                }
            }
            *(float4*)&out[(size_t)n * J + 8 * jv]     = acc[t][0];
            *(float4*)&out[(size_t)n * J + 8 * jv + 4] = acc[t][1];
        }
    }
}

// ---------------------------------------------------------------------------
extern "C" void kernel_launch(void* const* d_in, const int* in_sizes, int n_in,
                              void* d_out, int out_size)
{
    const float* features = (const float*)d_in[0];
    const int*   src      = (const int*)d_in[1];
    const int*   dst      = (const int*)d_in[2];
    const float* W1       = (const float*)d_in[3];
    const float* b1       = (const float*)d_in[4];
    const float* W2       = (const float*)d_in[5];
    const float* b2       = (const float*)d_in[6];
    const float* W3       = (const float*)d_in[7];
    const float* b3       = (const float*)d_in[8];

    float* z_out = (float*)d_out;                    // [50000, 32]
    float* recon = (float*)d_out + (size_t)NN * 32;  // [50000, 128]

    float* sp = nullptr;
    cudaGetSymbolAddress((void**)&sp, g_scratch);
    float* rs_out = sp + OFF_RS_OUT;
    float* rs_in  = sp + OFF_RS_IN;
    float* t1     = sp + OFF_T1;
    float* agg1   = sp + OFF_AGG1;
    float* t2     = sp + OFF_T2;
    float* t3     = sp + OFF_T3;
    float* agg3   = sp + OFF_AGG3;

    const int TB = 256;
    const int SPMM_BLKS = (NN * 32 + TB - 1) / TB;   // one warp per node

    // CSR build + norms (4 launches; zero + bases kernels eliminated)
    count_kernel<<<(NE + TB - 1) / TB, TB>>>(src, dst);
    scan_blocksum_rsqrt<<<NBLK, 256>>>();
    scan_final<<<NBLK, 256>>>();
    fill_kernel<<<(NE + TB - 1) / TB, TB>>>(src, dst);

    // Layer 1: t1 = (X @ W1) * rs_out ; agg1 = A t1   (TN=8, NB=256)
    // gemm1 also restores ICNT_SRC=0 for the next replay.
    gemm_kernel<128, 64, 32, 8, 0, 1, 1><<<(NN + 255) / 256, TB>>>(
        features, W1, nullptr, nullptr, rs_out, nullptr, t1);
    pull_spmm<64, 0><<<SPMM_BLKS, TB>>>(t1, agg1, nullptr, nullptr);

    // Layer 2: t2 = (relu(agg1*rs_in + b1) @ W2) * rs_out (TN=4, NB=256)
    //   then fused pull: z = (A t2)*rs_in + b2 -> z_out ; t3 = z*rs_out
    gemm_kernel<64, 32, 32, 4, 1, 1, 0><<<(NN + 255) / 256, TB>>>(
        agg1, W2, rs_in, b1, rs_out, nullptr, t2);
    pull_spmm<32, 1><<<SPMM_BLKS, TB>>>(t2, z_out, b2, t3);

    // Layer 3: agg3 = A t3 ; recon = (agg3*rs_in) @ W3 + b3 (TN=8, NB=128)
    pull_spmm<32, 0><<<SPMM_BLKS, TB>>>(t3, agg3, nullptr, nullptr);
    gemm_kernel<32, 128, 32, 8, 2, 2, 0><<<(NN + 127) / 128, TB>>>(
        agg3, W3, rs_in, nullptr, nullptr, b3, recon);
}